// round 9
// baseline (speedup 1.0000x reference)
#include <cuda_runtime.h>
#include <cuda_fp16.h>
#include <cstdint>
#include <cstddef>

#define CHANS 256
#define HWSZ  3136
#define BATCH 32
#define NPOS  (BATCH*HWSZ)        // 100352
#define STEPS 10
#define SCOPE 15
#define PADC  7

#define TILE_P 128                // positions per tile
#define KC     32                 // cin per chunk
#define NCHUNK (CHANS/KC)         // 8
#define NTILES (NPOS/TILE_P)      // 784
#define NSM    148                // persistent grid

// u64-entry strides; (2*RS) % 32 == 8 -> 8q+2g bank permutation (conflict-free)
#define RSX    132                // X: 128 pos + pad (u64 units)
#define RSW    260                // W: 256 cout + pad (u64 units)
#define XBUF64 (8*RSX)            // 1056 u64 per X buffer (8 pair-rows x 128 pos)
#define WRES64 (64*RSW)           // 16640 u64 resident W
#define SMEM_BYTES ((4*XBUF64 + WRES64)*8)   // 166912 B

// W_eff = sum_{k=0..10} T^k, fp16: g_wh[cin][cout]
__device__ __half g_wh[CHANS*CHANS];

// ---------------- helpers ----------------
__device__ __forceinline__ uint32_t pkh2(float hi, float lo){
    uint32_t r; asm("cvt.rn.f16x2.f32 %0, %1, %2;" : "=r"(r) : "f"(hi), "f"(lo)); return r;
}
__device__ __forceinline__ uint32_t prmt(uint32_t a, uint32_t b, uint32_t sel){
    uint32_t r; asm("prmt.b32 %0, %1, %2, %3;" : "=r"(r) : "r"(a), "r"(b), "r"(sel)); return r;
}
__device__ __forceinline__ void mma16(float* d, const uint32_t* a, uint32_t b0, uint32_t b1){
    asm volatile("mma.sync.aligned.m16n8k16.row.col.f32.f16.f16.f32 "
        "{%0,%1,%2,%3}, {%4,%5,%6,%7}, {%8,%9}, {%0,%1,%2,%3};"
        : "+f"(d[0]), "+f"(d[1]), "+f"(d[2]), "+f"(d[3])
        : "r"(a[0]), "r"(a[1]), "r"(a[2]), "r"(a[3]), "r"(b0), "r"(b1));
}

// ---------------- Kernel 1: build W_eff (fp16) ----------------
// Block j: column j of S = sum_{k=0..STEPS} T^k via S_{s+1} = I + T*S_s (exact,
// includes zero-pad boundaries). Thread i holds S[i][j] = W[cout=i][cin=j].
__global__ void build_weff_kernel(const float* __restrict__ w){
    __shared__ float sv[CHANS + 2*PADC];
    const int i = threadIdx.x, j = blockIdx.x;
    if (i < PADC){ sv[i] = 0.f; sv[CHANS + PADC + i] = 0.f; }
    float wv[SCOPE];
#pragma unroll
    for (int k = 0; k < SCOPE; ++k) wv[k] = w[k];
    float v = (i == j) ? 1.f : 0.f;
    for (int s = 0; s < STEPS; ++s){
        __syncthreads();
        sv[PADC + i] = v;
        __syncthreads();
        float acc = (i == j) ? 1.f : 0.f;
#pragma unroll
        for (int k = 0; k < SCOPE; ++k) acc = fmaf(wv[k], sv[i + k], acc);
        v = acc;
    }
    g_wh[j * CHANS + i] = __float2half_rn(v);
}

// ---------------- Kernel 2: persistent GEMM out = W_eff * X ----------------
// SMEM entries are u64 = {k-pair of k2-row r (lo), k-pair of k2-row r+4 (hi)}:
// every mma fragment pair = one conflict-free LDS.64. W fully resident; X in a
// 4-buffer ring, STS 2 chunks ahead / LDG 3 ahead, barrier every 2 chunks.
__global__ void __launch_bounds__(512, 1)
gemm_kernel(const float* __restrict__ x, float* __restrict__ out){
    extern __shared__ uint2 smu[];
    uint2* xring = smu;                // 4 x [8][RSX]
    uint2* wres  = smu + 4*XBUF64;     // [64][RSW]

    const int tid  = threadIdx.x;
    const int lane = tid & 31;
    const int wid  = tid >> 5;
    const int g = lane >> 2, q = lane & 3;
    const int wp = wid >> 2, wc = wid & 3;
    const int bid = blockIdx.x;

    // ---- one-time W load: 8192 iterations of 2 entries ----
    // entry [row=c*8+ks*4+q][n] = {h2(w[c0][n],w[c0+1][n]), h2(w[c0+8][n],w[c0+9][n])}
    // c0 = 32c + 16ks + 2q
#pragma unroll
    for (int i = 0; i < 16; ++i){
        int id  = tid + i * 512;            // 0..8191
        int n2  = (id & 127) << 1;
        int row = id >> 7;                  // 0..63
        int c = row >> 3, pr = row & 7;
        int c0 = 32 * c + 16 * (pr >> 2) + 2 * (pr & 3);
        const __half* base = g_wh + (size_t)c0 * CHANS + n2;
        uint32_t A = *(const uint32_t*)base;
        uint32_t B = *(const uint32_t*)(base + CHANS);
        uint32_t C = *(const uint32_t*)(base + 8 * CHANS);
        uint32_t D = *(const uint32_t*)(base + 9 * CHANS);
        uint4 e;
        e.x = prmt(A, B, 0x5410);  e.y = prmt(C, D, 0x5410);   // entry n2
        e.z = prmt(A, B, 0x7632);  e.w = prmt(C, D, 0x7632);   // entry n2+1
        *(uint4*)(wres + row * RSW + n2) = e;
    }

    const int ntiles = (NTILES - bid + NSM - 1) / NSM;   // 5 or 6
    const int gend   = ntiles * NCHUNK;                  // 40 or 48 (even)

    // X staging: thread -> pair-row r (0..7), 2 consecutive pos
    const int sr  = tid >> 6;              // 0..7
    const int spp = (tid & 63) << 1;       // 0..126
    const int scr = ((sr >> 2) << 4) + ((sr & 3) << 1);  // channel base within chunk

    float2 f0, f1, f8, f9;
    auto ldg_x = [&](int gc){
        int t = gc >> 3, c = gc & 7;
        int tile = bid + t * NSM;
        int sn = tile * TILE_P + spp;      // 2|3136 -> no batch straddle
        int b = sn / HWSZ, p = sn - b * HWSZ;
        const float* s = x + ((size_t)b * CHANS + (size_t)(c * KC + scr)) * HWSZ + p;
        f0 = *(const float2*)s;
        f1 = *(const float2*)(s + HWSZ);
        f8 = *(const float2*)(s + 8 * HWSZ);
        f9 = *(const float2*)(s + 9 * HWSZ);
    };
    auto sts_x = [&](uint2* buf){
        uint4 e;
        e.x = pkh2(f1.x, f0.x);  e.y = pkh2(f9.x, f8.x);   // pos spp
        e.z = pkh2(f1.y, f0.y);  e.w = pkh2(f9.y, f8.y);   // pos spp+1
        *(uint4*)(buf + sr * RSX + spp) = e;
    };

    float acc[2][8][4];
#pragma unroll
    for (int mt = 0; mt < 2; ++mt)
#pragma unroll
        for (int nt = 0; nt < 8; ++nt)
#pragma unroll
            for (int r = 0; r < 4; ++r) acc[mt][nt][r] = 0.f;

    // prologue: chunks 0,1 into ring, chunk 2 into regs
    ldg_x(0); sts_x(xring);
    ldg_x(1); sts_x(xring + XBUF64);
    ldg_x(2);
    __syncthreads();   // covers resident W + buf0/1

    for (int gc = 0; gc < gend; ++gc){
        const uint2* xb = xring + (gc & 3) * XBUF64;
        const uint2* wb = wres + (gc & 7) * 8 * RSW;
#pragma unroll
        for (int ks = 0; ks < 2; ++ks){
            const uint2* xk = xb + (ks * 4 + q) * RSX + wp * 32;
            uint32_t a[2][4];
#pragma unroll
            for (int mt = 0; mt < 2; ++mt){
                int p0 = mt * 16 + g;
                uint2 u = xk[p0];          // {row r, row r+4} at pos
                uint2 v = xk[p0 + 8];      // same at pos+8
                a[mt][0] = u.x;  a[mt][2] = u.y;
                a[mt][1] = v.x;  a[mt][3] = v.y;
            }
            const uint2* wk = wb + (ks * 4 + q) * RSW + wc * 64 + g;
#pragma unroll
            for (int nt = 0; nt < 8; ++nt){
                uint2 bv = wk[nt * 8];     // {b0, b1}
                mma16(acc[0][nt], a[0], bv.x, bv.y);
                mma16(acc[1][nt], a[1], bv.x, bv.y);
            }
        }

        // stage ahead: STS chunk gc+2 (in regs), LDG chunk gc+3
        if (gc + 2 < gend){
            sts_x(xring + ((gc + 2) & 3) * XBUF64);
            if (gc + 3 < gend) ldg_x(gc + 3);
        }

        // per-tile epilogue (overlaps in-flight LDGs)
        if ((gc & 7) == 7){
            int tile = bid + (gc >> 3) * NSM;
#pragma unroll
            for (int mt = 0; mt < 2; ++mt){
#pragma unroll
                for (int rs = 0; rs < 2; ++rs){
                    int pos = tile * TILE_P + wp * 32 + mt * 16 + g + rs * 8;
                    int b = pos / HWSZ, p = pos - b * HWSZ;
                    float* ob = out + ((size_t)b * CHANS + (size_t)(wc * 64 + 2 * q)) * HWSZ + p;
#pragma unroll
                    for (int nt = 0; nt < 8; ++nt){
                        ob[(size_t)(nt * 8) * HWSZ]     = acc[mt][nt][rs * 2 + 0];
                        ob[(size_t)(nt * 8 + 1) * HWSZ] = acc[mt][nt][rs * 2 + 1];
                    }
                }
            }
#pragma unroll
            for (int mt = 0; mt < 2; ++mt)
#pragma unroll
                for (int nt = 0; nt < 8; ++nt)
#pragma unroll
                    for (int r = 0; r < 4; ++r) acc[mt][nt][r] = 0.f;
        }

        // barrier every 2 chunks (safety: chunk c STS'd at c-2; a barrier lies
        // at end of c-2 or c-1; WAR spans 4 iterations with >=1 barrier between)
        if ((gc & 1) == 1 && gc + 1 < gend) __syncthreads();
    }
}

// ---------------- launch ----------------
extern "C" void kernel_launch(void* const* d_in, const int* in_sizes, int n_in,
                              void* d_out, int out_size)
{
    const float* acts = (const float*)d_in[0];
    const float* wrec = (const float*)d_in[1];
    float* out        = (float*)d_out;
    (void)in_sizes; (void)n_in; (void)out_size;

    cudaFuncSetAttribute(gemm_kernel, cudaFuncAttributeMaxDynamicSharedMemorySize, SMEM_BYTES);

    build_weff_kernel<<<CHANS, CHANS>>>(wrec);
    gemm_kernel<<<NSM, 512, SMEM_BYTES>>>(acts, out);
}

// round 10
// speedup vs baseline: 1.0508x; 1.0508x over previous
#include <cuda_runtime.h>
#include <cuda_fp16.h>
#include <cstdint>
#include <cstddef>

#define CHANS 256
#define HWSZ  3136
#define BATCH 32
#define NPOS  (BATCH*HWSZ)        // 100352
#define STEPS 10
#define SCOPE 15
#define PADC  7

#define TILE_P 128                // positions per tile
#define KC     32                 // cin per chunk
#define NCHUNK (CHANS/KC)         // 8
#define NTILES (NPOS/TILE_P)      // 784
#define NSM    148                // persistent grid

// fp16 rows, strides in 4B words chosen %32==4 -> ldmatrix 8-row tiles are
// bank-conflict-free (4k mod 32 covers 0,4,...,28).
#define RSXW   68                 // X row: 128 pos fp16 = 64 words + 4 pad
#define RSWW   132                // W row: 256 cout fp16 = 128 words + 4 pad
#define XBUFW  (32*RSXW)          // 2176 words per X buffer (32 k-rows)
#define WRESW  (256*RSWW)         // 33792 words resident W
#define XBUF_BYTES (XBUFW*4)      // 8704
#define SMEM_BYTES ((2*XBUFW + WRESW)*4)   // 152576 B

// W_eff = sum_{k=0..10} T^k, fp16: g_wh[cin][cout]
__device__ __half g_wh[CHANS*CHANS];

// ---------------- helpers ----------------
__device__ __forceinline__ uint32_t smem_u32(const void* p){
    uint32_t a;
    asm("{ .reg .u64 t; cvta.to.shared.u64 t, %1; cvt.u32.u64 %0, t; }" : "=r"(a) : "l"(p));
    return a;
}
__device__ __forceinline__ uint32_t pkh2(float hi, float lo){
    uint32_t r; asm("cvt.rn.f16x2.f32 %0, %1, %2;" : "=r"(r) : "f"(hi), "f"(lo)); return r;
}
__device__ __forceinline__ void ldmx4t(uint32_t* r, uint32_t addr){
    asm volatile("ldmatrix.sync.aligned.m8n8.x4.trans.shared.b16 {%0,%1,%2,%3}, [%4];"
        : "=r"(r[0]), "=r"(r[1]), "=r"(r[2]), "=r"(r[3]) : "r"(addr));
}
__device__ __forceinline__ void mma16(float* d, const uint32_t* a, uint32_t b0, uint32_t b1){
    asm volatile("mma.sync.aligned.m16n8k16.row.col.f32.f16.f16.f32 "
        "{%0,%1,%2,%3}, {%4,%5,%6,%7}, {%8,%9}, {%0,%1,%2,%3};"
        : "+f"(d[0]), "+f"(d[1]), "+f"(d[2]), "+f"(d[3])
        : "r"(a[0]), "r"(a[1]), "r"(a[2]), "r"(a[3]), "r"(b0), "r"(b1));
}

// ---------------- Kernel 1: build W_eff (fp16) ----------------
// Block j: column j of S = sum_{k=0..STEPS} T^k via S_{s+1} = I + T*S_s (exact,
// includes zero-pad boundaries). Thread i holds S[i][j] = W[cout=i][cin=j];
// writes g_wh[cin=j][cout=i].
__global__ void build_weff_kernel(const float* __restrict__ w){
    __shared__ float sv[CHANS + 2*PADC];
    const int i = threadIdx.x, j = blockIdx.x;
    if (i < PADC){ sv[i] = 0.f; sv[CHANS + PADC + i] = 0.f; }
    float wv[SCOPE];
#pragma unroll
    for (int k = 0; k < SCOPE; ++k) wv[k] = w[k];
    float v = (i == j) ? 1.f : 0.f;
    for (int s = 0; s < STEPS; ++s){
        __syncthreads();
        sv[PADC + i] = v;
        __syncthreads();
        float acc = (i == j) ? 1.f : 0.f;
#pragma unroll
        for (int k = 0; k < SCOPE; ++k) acc = fmaf(wv[k], sv[i + k], acc);
        v = acc;
    }
    g_wh[j * CHANS + i] = __float2half_rn(v);
}

// ---------------- Kernel 2: persistent GEMM out = W_eff * X ----------------
// 148 persistent CTAs, 512 threads. Operands in SMEM as plain fp16 [k][col];
// all mma fragments loaded via ldmatrix.x4.trans (conflict-free row strides).
// W fully resident; X double-buffered, one barrier per chunk (R8 scheme).
__global__ void __launch_bounds__(512, 1)
gemm_kernel(const float* __restrict__ x, float* __restrict__ out){
    extern __shared__ uint32_t smu[];
    uint32_t* xbuf = smu;              // 2 x [32][RSXW]
    uint32_t* wres = smu + 2*XBUFW;    // [256][RSWW]

    const int tid  = threadIdx.x;
    const int lane = tid & 31;
    const int wid  = tid >> 5;
    const int g = lane >> 2, q = lane & 3;
    const int wp = wid >> 2, wc = wid & 3;
    const int bid = blockIdx.x;

    // ---- one-time W load: plain copy g_wh rows -> [k][cout] fp16 ----
#pragma unroll
    for (int i = 0; i < 16; ++i){
        int id  = tid + i * 512;           // 0..8191
        int row = id >> 5;                 // 0..255 (cin)
        int c8  = (id & 31) << 3;          // cout group of 8
        const uint4 v = *(const uint4*)(g_wh + (size_t)row * CHANS + c8);
        *(uint4*)(wres + row * RSWW + (c8 >> 1)) = v;
    }

    const int ntiles = (NTILES - bid + NSM - 1) / NSM;   // 5 or 6
    const int gend   = ntiles * NCHUNK;                  // 40 or 48

    // X staging: thread -> (k row 0..31, 8 consecutive pos); 8|3136 -> no straddle
    const int sk  = tid >> 4;              // 0..31
    const int sp8 = (tid & 15) << 3;       // 0..120

    float4 xf0, xf1;
    auto ldg_x = [&](int gc){
        int t = gc >> 3, c = gc & 7;
        int tile = bid + t * NSM;
        int sn = tile * TILE_P + sp8;
        int b = sn / HWSZ, p = sn - b * HWSZ;
        const float* s = x + ((size_t)b * CHANS + (size_t)(c * KC + sk)) * HWSZ + p;
        xf0 = *(const float4*)s;
        xf1 = *(const float4*)(s + 4);
    };
    auto sts_x = [&](uint32_t* buf){
        uint4 v;
        v.x = pkh2(xf0.y, xf0.x);  v.y = pkh2(xf0.w, xf0.z);
        v.z = pkh2(xf1.y, xf1.x);  v.w = pkh2(xf1.w, xf1.z);
        *(uint4*)(buf + sk * RSXW + (sp8 >> 1)) = v;
    };

    // ldmatrix per-lane base addresses (bytes)
    // A tiles (x4): r0 = (k 0-7, pos 0-7), r1 = (k 0-7, pos 8-15),
    //               r2 = (k 8-15, pos 0-7), r3 = (k 8-15, pos 8-15)
    const int a_k = (lane & 7) + ((lane >> 4) << 3);        // lanes 16-31: +8 k
    const int a_p = ((lane >> 3) & 1) << 3;                 // lanes 8-15,24-31: +8 pos
    const uint32_t xaddr0 = smem_u32(xbuf) + (uint32_t)(a_k * (RSXW*4) + (wp * 32 + a_p) * 2);
    // B tiles (x4): r0 = (k 0-7, cout j*16..+7), r1 = (k 8-15, same couts),
    //               r2 = (k 0-7, couts +8), r3 = (k 8-15, couts +8)
    const int b_k = (lane & 7) + (((lane >> 3) & 1) << 3);  // lanes 8-15,24-31: +8 k
    const int b_c = ((lane >> 4) << 3);                     // lanes 16-31: +8 cout
    const uint32_t waddr0 = smem_u32(wres) + (uint32_t)(b_k * (RSWW*4) + (wc * 64 + b_c) * 2);

    float acc[2][8][4];
#pragma unroll
    for (int mt = 0; mt < 2; ++mt)
#pragma unroll
        for (int nt = 0; nt < 8; ++nt)
#pragma unroll
            for (int r = 0; r < 4; ++r) acc[mt][nt][r] = 0.f;

    // prologue: chunk0 into smem, chunk1 into regs
    ldg_x(0);
    sts_x(xbuf);
    ldg_x(1);
    __syncthreads();   // covers resident W + buf0

    for (int gc = 0; gc < gend; ++gc){
        const uint32_t xa_c = xaddr0 + (uint32_t)((gc & 1) * XBUF_BYTES);
        const uint32_t wa_c = waddr0 + (uint32_t)((gc & 7) * 32 * (RSWW*4));
#pragma unroll
        for (int ks = 0; ks < 2; ++ks){
            const uint32_t xa_k = xa_c + (uint32_t)(ks * 16 * (RSXW*4));
            const uint32_t wa_k = wa_c + (uint32_t)(ks * 16 * (RSWW*4));
            uint32_t a[2][4];
            ldmx4t(a[0], xa_k);            // mt=0: pos wp*32 + 0..15
            ldmx4t(a[1], xa_k + 32);       // mt=1: pos +16 (16 fp16 = 32B)
#pragma unroll
            for (int j = 0; j < 4; ++j){
                uint32_t b[4];             // {b0 nt=2j, b1 nt=2j, b0 nt=2j+1, b1 nt=2j+1}
                ldmx4t(b, wa_k + (uint32_t)(j * 32));
                mma16(acc[0][2*j],   a[0], b[0], b[1]);
                mma16(acc[1][2*j],   a[1], b[0], b[1]);
                mma16(acc[0][2*j+1], a[0], b[2], b[3]);
                mma16(acc[1][2*j+1], a[1], b[2], b[3]);
            }
        }

        // stage next chunk (single-sync safety: buffer (gc+1)&1 was last read in
        // iteration gc-1, fenced by the barrier at end of gc-1)
        const bool more = (gc + 1 < gend);
        if (more){
            sts_x(xbuf + ((gc + 1) & 1) * XBUFW);
            if (gc + 2 < gend) ldg_x(gc + 2);
        }

        // per-tile epilogue (overlaps in-flight LDGs)
        if ((gc & 7) == 7){
            int tile = bid + (gc >> 3) * NSM;
#pragma unroll
            for (int mt = 0; mt < 2; ++mt){
#pragma unroll
                for (int rs = 0; rs < 2; ++rs){
                    int pos = tile * TILE_P + wp * 32 + mt * 16 + g + rs * 8;
                    int b = pos / HWSZ, p = pos - b * HWSZ;
                    float* ob = out + ((size_t)b * CHANS + (size_t)(wc * 64 + 2 * q)) * HWSZ + p;
#pragma unroll
                    for (int nt = 0; nt < 8; ++nt){
                        ob[(size_t)(nt * 8) * HWSZ]     = acc[mt][nt][rs * 2 + 0];
                        ob[(size_t)(nt * 8 + 1) * HWSZ] = acc[mt][nt][rs * 2 + 1];
                    }
                }
            }
#pragma unroll
            for (int mt = 0; mt < 2; ++mt)
#pragma unroll
                for (int nt = 0; nt < 8; ++nt)
#pragma unroll
                    for (int r = 0; r < 4; ++r) acc[mt][nt][r] = 0.f;
        }

        if (more) __syncthreads();
    }
}

// ---------------- launch ----------------
extern "C" void kernel_launch(void* const* d_in, const int* in_sizes, int n_in,
                              void* d_out, int out_size)
{
    const float* acts = (const float*)d_in[0];
    const float* wrec = (const float*)d_in[1];
    float* out        = (float*)d_out;
    (void)in_sizes; (void)n_in; (void)out_size;

    cudaFuncSetAttribute(gemm_kernel, cudaFuncAttributeMaxDynamicSharedMemorySize, SMEM_BYTES);

    build_weff_kernel<<<CHANS, CHANS>>>(wrec);
    gemm_kernel<<<NSM, 512, SMEM_BYTES>>>(acts, out);
}

// round 11
// speedup vs baseline: 1.2138x; 1.1551x over previous
#include <cuda_runtime.h>
#include <cuda_fp16.h>
#include <cstdint>
#include <cstddef>

#define CHANS 256
#define HWSZ  3136
#define BATCH 32
#define NPOS  (BATCH*HWSZ)        // 100352
#define STEPS 10
#define SCOPE 15
#define PADC  7

#define TILE_P 128                // positions per tile
#define KC     64                 // cin per chunk
#define NCHUNK (CHANS/KC)         // 4
#define NTILES (NPOS/TILE_P)      // 784
#define NSM    148                // persistent grid

// fp16 rows, strides in 4B words %32==4 -> ldmatrix 8-row tiles conflict-free
#define RSXW   68                 // X row: 128 pos fp16 = 64 words + 4 pad
#define RSWW   132                // W row: 256 cout fp16 = 128 words + 4 pad
#define XBUFW  (KC*RSXW)          // 4352 words per X buffer (64 k-rows)
#define WRESW  (256*RSWW)         // 33792 words resident W
#define XBUF_BYTES (XBUFW*4)      // 17408
#define SMEM_BYTES ((2*XBUFW + WRESW)*4)   // 169984 B

// W_eff = sum_{k=0..10} T^k, fp16: g_wh[cin][cout]
__device__ __half g_wh[CHANS*CHANS];

// ---------------- helpers ----------------
__device__ __forceinline__ uint32_t smem_u32(const void* p){
    uint32_t a;
    asm("{ .reg .u64 t; cvta.to.shared.u64 t, %1; cvt.u32.u64 %0, t; }" : "=r"(a) : "l"(p));
    return a;
}
__device__ __forceinline__ uint32_t pkh2(float hi, float lo){
    uint32_t r; asm("cvt.rn.f16x2.f32 %0, %1, %2;" : "=r"(r) : "f"(hi), "f"(lo)); return r;
}
__device__ __forceinline__ void ldmx4t(uint32_t* r, uint32_t addr){
    asm volatile("ldmatrix.sync.aligned.m8n8.x4.trans.shared.b16 {%0,%1,%2,%3}, [%4];"
        : "=r"(r[0]), "=r"(r[1]), "=r"(r[2]), "=r"(r[3]) : "r"(addr));
}
__device__ __forceinline__ void mma16(float* d, const uint32_t* a, uint32_t b0, uint32_t b1){
    asm volatile("mma.sync.aligned.m16n8k16.row.col.f32.f16.f16.f32 "
        "{%0,%1,%2,%3}, {%4,%5,%6,%7}, {%8,%9}, {%0,%1,%2,%3};"
        : "+f"(d[0]), "+f"(d[1]), "+f"(d[2]), "+f"(d[3])
        : "r"(a[0]), "r"(a[1]), "r"(a[2]), "r"(a[3]), "r"(b0), "r"(b1));
}

// ---------------- Kernel 1: build W_eff (fp16) ----------------
// Block j: column j of S = sum_{k=0..STEPS} T^k via S_{s+1} = I + T*S_s (exact,
// includes zero-pad boundaries). Thread i holds S[i][j] = W[cout=i][cin=j];
// writes g_wh[cin=j][cout=i].
__global__ void build_weff_kernel(const float* __restrict__ w){
    __shared__ float sv[CHANS + 2*PADC];
    const int i = threadIdx.x, j = blockIdx.x;
    if (i < PADC){ sv[i] = 0.f; sv[CHANS + PADC + i] = 0.f; }
    float wv[SCOPE];
#pragma unroll
    for (int k = 0; k < SCOPE; ++k) wv[k] = w[k];
    float v = (i == j) ? 1.f : 0.f;
    for (int s = 0; s < STEPS; ++s){
        __syncthreads();
        sv[PADC + i] = v;
        __syncthreads();
        float acc = (i == j) ? 1.f : 0.f;
#pragma unroll
        for (int k = 0; k < SCOPE; ++k) acc = fmaf(wv[k], sv[i + k], acc);
        v = acc;
    }
    g_wh[j * CHANS + i] = __float2half_rn(v);
}

// ---------------- Kernel 2: persistent GEMM out = W_eff * X ----------------
// 148 persistent CTAs, 512 threads. Operands in SMEM as plain fp16 [k][col];
// fragments via ldmatrix.x4.trans. W fully resident. X double-buffered in
// KC=64 chunks; LDG issued at iteration top, STS at bottom -> a full chunk of
// compute covers DRAM latency. One barrier per chunk (4 per tile).
__global__ void __launch_bounds__(512, 1)
gemm_kernel(const float* __restrict__ x, float* __restrict__ out){
    extern __shared__ uint32_t smu[];
    uint32_t* xbuf = smu;              // 2 x [64][RSXW]
    uint32_t* wres = smu + 2*XBUFW;    // [256][RSWW]

    const int tid  = threadIdx.x;
    const int lane = tid & 31;
    const int wid  = tid >> 5;
    const int g = lane >> 2, q = lane & 3;
    const int wp = wid >> 2, wc = wid & 3;
    const int bid = blockIdx.x;

    // ---- one-time W load: plain copy g_wh rows -> [k][cout] fp16 ----
#pragma unroll
    for (int i = 0; i < 16; ++i){
        int id  = tid + i * 512;           // 0..8191
        int row = id >> 5;                 // 0..255 (cin)
        int c8  = (id & 31) << 3;          // cout group of 8
        const uint4 v = *(const uint4*)(g_wh + (size_t)row * CHANS + c8);
        *(uint4*)(wres + row * RSWW + (c8 >> 1)) = v;
    }

    const int ntiles = (NTILES - bid + NSM - 1) / NSM;   // 5 or 6
    const int gend   = ntiles * NCHUNK;                  // 20 or 24

    // X staging: thread -> (k rows sk, sk+32; 8 consecutive pos); 8|3136 -> no straddle
    const int sk  = tid >> 4;              // 0..31
    const int sp8 = (tid & 15) << 3;       // 0..120

    float4 xf[4];
    auto ldg_x = [&](int gc){
        int t = gc >> 2, c = gc & 3;
        int tile = bid + t * NSM;
        int sn = tile * TILE_P + sp8;
        int b = sn / HWSZ, p = sn - b * HWSZ;
        const float* s = x + ((size_t)b * CHANS + (size_t)(c * KC + sk)) * HWSZ + p;
        xf[0] = *(const float4*)s;
        xf[1] = *(const float4*)(s + 4);
        xf[2] = *(const float4*)(s + 32 * HWSZ);
        xf[3] = *(const float4*)(s + 32 * HWSZ + 4);
    };
    auto sts_x = [&](uint32_t* buf){
        uint4 v0, v1;
        v0.x = pkh2(xf[0].y, xf[0].x);  v0.y = pkh2(xf[0].w, xf[0].z);
        v0.z = pkh2(xf[1].y, xf[1].x);  v0.w = pkh2(xf[1].w, xf[1].z);
        v1.x = pkh2(xf[2].y, xf[2].x);  v1.y = pkh2(xf[2].w, xf[2].z);
        v1.z = pkh2(xf[3].y, xf[3].x);  v1.w = pkh2(xf[3].w, xf[3].z);
        *(uint4*)(buf + sk * RSXW + (sp8 >> 1))        = v0;
        *(uint4*)(buf + (sk + 32) * RSXW + (sp8 >> 1)) = v1;
    };

    // ldmatrix per-lane base addresses (bytes)
    const int a_k = (lane & 7) + ((lane >> 4) << 3);        // A: lanes 16-31 -> +8 k
    const int a_p = ((lane >> 3) & 1) << 3;                 // A: lanes 8-15,24-31 -> +8 pos
    const uint32_t xaddr0 = smem_u32(xbuf) + (uint32_t)(a_k * (RSXW*4) + (wp * 32 + a_p) * 2);
    const int b_k = (lane & 7) + (((lane >> 3) & 1) << 3);  // B: lanes 8-15,24-31 -> +8 k
    const int b_c = ((lane >> 4) << 3);                     // B: lanes 16-31 -> +8 cout
    const uint32_t waddr0 = smem_u32(wres) + (uint32_t)(b_k * (RSWW*4) + (wc * 64 + b_c) * 2);

    float acc[2][8][4];
#pragma unroll
    for (int mt = 0; mt < 2; ++mt)
#pragma unroll
        for (int nt = 0; nt < 8; ++nt)
#pragma unroll
            for (int r = 0; r < 4; ++r) acc[mt][nt][r] = 0.f;

    // prologue: chunk0 into smem
    ldg_x(0);
    sts_x(xbuf);
    __syncthreads();   // covers resident W + buf0

    for (int gc = 0; gc < gend; ++gc){
        const bool more = (gc + 1 < gend);
        if (more) ldg_x(gc + 1);           // issued at top: full chunk of cover

        const uint32_t xa_c = xaddr0 + (uint32_t)((gc & 1) * XBUF_BYTES);
        const uint32_t wa_c = waddr0 + (uint32_t)((gc & 3) * KC * (RSWW*4));
#pragma unroll
        for (int ks = 0; ks < 4; ++ks){
            const uint32_t xa_k = xa_c + (uint32_t)(ks * 16 * (RSXW*4));
            const uint32_t wa_k = wa_c + (uint32_t)(ks * 16 * (RSWW*4));
            uint32_t a[2][4];
            ldmx4t(a[0], xa_k);            // pos wp*32 + 0..15
            ldmx4t(a[1], xa_k + 32);       // pos +16
#pragma unroll
            for (int j = 0; j < 4; ++j){
                uint32_t b[4];
                ldmx4t(b, wa_k + (uint32_t)(j * 32));
                mma16(acc[0][2*j],   a[0], b[0], b[1]);
                mma16(acc[1][2*j],   a[1], b[0], b[1]);
                mma16(acc[0][2*j+1], a[0], b[2], b[3]);
                mma16(acc[1][2*j+1], a[1], b[2], b[3]);
            }
        }

        // STS at bottom (single-sync safety: buffer (gc+1)&1 last read at gc-1,
        // fenced by the barrier at end of gc-1)
        if (more) sts_x(xbuf + ((gc + 1) & 1) * XBUFW);

        // per-tile epilogue (overlaps STS completion / barrier)
        if ((gc & 3) == 3){
            int tile = bid + (gc >> 2) * NSM;
#pragma unroll
            for (int mt = 0; mt < 2; ++mt){
#pragma unroll
                for (int rs = 0; rs < 2; ++rs){
                    int pos = tile * TILE_P + wp * 32 + mt * 16 + g + rs * 8;
                    int b = pos / HWSZ, p = pos - b * HWSZ;
                    float* ob = out + ((size_t)b * CHANS + (size_t)(wc * 64 + 2 * q)) * HWSZ + p;
#pragma unroll
                    for (int nt = 0; nt < 8; ++nt){
                        ob[(size_t)(nt * 8) * HWSZ]     = acc[mt][nt][rs * 2 + 0];
                        ob[(size_t)(nt * 8 + 1) * HWSZ] = acc[mt][nt][rs * 2 + 1];
                    }
                }
            }
#pragma unroll
            for (int mt = 0; mt < 2; ++mt)
#pragma unroll
                for (int nt = 0; nt < 8; ++nt)
#pragma unroll
                    for (int r = 0; r < 4; ++r) acc[mt][nt][r] = 0.f;
        }

        if (more) __syncthreads();
    }
}

// ---------------- launch ----------------
extern "C" void kernel_launch(void* const* d_in, const int* in_sizes, int n_in,
                              void* d_out, int out_size)
{
    const float* acts = (const float*)d_in[0];
    const float* wrec = (const float*)d_in[1];
    float* out        = (float*)d_out;
    (void)in_sizes; (void)n_in; (void)out_size;

    cudaFuncSetAttribute(gemm_kernel, cudaFuncAttributeMaxDynamicSharedMemorySize, SMEM_BYTES);

    build_weff_kernel<<<CHANS, CHANS>>>(wrec);
    gemm_kernel<<<NSM, 512, SMEM_BYTES>>>(acts, out);
}